// round 1
// baseline (speedup 1.0000x reference)
#include <cuda_runtime.h>

// RecurrentGCN_87926570483780
//
// Reference math collapses exactly:
//   - K=1 DConv: edge data is dead code.
//   - H0 = zeros  -> Z,R,Ht depend only on X; cell = (1-Z)*Ht.
//   - Final op: log_softmax over a size-1 axis == 0 identically,
//     regardless of the linear layer's value.
// Therefore the output is EXACTLY zeros([N, 1]) for all inputs.
// The optimal kernel is a vectorized zero-fill of d_out.

__global__ void zero_fill_f4(float4* __restrict__ out4, int n4) {
    int i = blockIdx.x * blockDim.x + threadIdx.x;
    if (i < n4) {
        out4[i] = make_float4(0.f, 0.f, 0.f, 0.f);
    }
}

__global__ void zero_fill_tail(float* __restrict__ out, int start, int n) {
    int i = start + blockIdx.x * blockDim.x + threadIdx.x;
    if (i < n) {
        out[i] = 0.f;
    }
}

extern "C" void kernel_launch(void* const* d_in, const int* in_sizes, int n_in,
                              void* d_out, int out_size) {
    (void)d_in; (void)in_sizes; (void)n_in;

    float* out = (float*)d_out;
    int n4 = out_size >> 2;          // out_size = 250000 -> n4 = 62500 (exact)
    int rem_start = n4 << 2;

    if (n4 > 0) {
        int threads = 256;
        int blocks = (n4 + threads - 1) / threads;
        zero_fill_f4<<<blocks, threads>>>((float4*)out, n4);
    }
    if (rem_start < out_size) {
        int rem = out_size - rem_start;
        int threads = 128;
        int blocks = (rem + threads - 1) / threads;
        zero_fill_tail<<<blocks, threads>>>(out, rem_start, out_size);
    }
}

// round 2
// speedup vs baseline: 1.0066x; 1.0066x over previous
#include <cuda_runtime.h>

// RecurrentGCN_87926570483780
//
// Reference math collapses exactly:
//   - K=1 DConv: edge data is dead code.
//   - H0 = zeros -> Z,R depend only on X; cell = (1-Z)*Ht.
//   - Final op: log_softmax over a size-1 axis == 0 identically.
// Output is EXACTLY zeros([N,1]) for all inputs -> single zero-fill launch.
//
// One kernel, one graph node: each thread does one STG.128 (predicated),
// last thread mops up any scalar tail (none for out_size=250000, but kept
// for generality at zero cost).

__global__ void __launch_bounds__(256) zero_fill_one(float* __restrict__ out, int n) {
    int i = (blockIdx.x * blockDim.x + threadIdx.x) << 2;
    if (i + 3 < n) {
        *reinterpret_cast<float4*>(out + i) = make_float4(0.f, 0.f, 0.f, 0.f);
    } else {
        for (; i < n; ++i) out[i] = 0.f;
    }
}

extern "C" void kernel_launch(void* const* d_in, const int* in_sizes, int n_in,
                              void* d_out, int out_size) {
    (void)d_in; (void)in_sizes; (void)n_in;

    int threads = 256;
    int n4 = (out_size + 3) >> 2;                 // float4 slots incl. tail
    int blocks = (n4 + threads - 1) / threads;    // 245 for out_size=250000
    zero_fill_one<<<blocks, threads>>>((float*)d_out, out_size);
}